// round 4
// baseline (speedup 1.0000x reference)
#include <cuda_runtime.h>
#include <cstdint>

#define BB 16
#define NN 8192
#define HH 128
#define GG 10
#define DCC 16
#define NBLK 6
#define K1 154        // H + G + DC (local cat width)
#define KPROJ0 272    // 2H + DC
#define KBLK 282      // 2H + G + DC
#define CATS 132      // padded cat row stride (floats)
#define W1S 155       // padded l1w row stride
#define W2S 129       // padded l2w row stride
#define HTS 65        // h_l staging row stride (float2 units)

// SMEM layout for the local kernel (float offsets)
#define SM_CAT 0
#define SM_BUF (K1*CATS)                 // 20328 : w1 (128x155) then reused as hT (128x65 f2)
#define SM_W2  (SM_BUF + HH*W1S)         // 40168 : w2 (128x129)
#define SM_B1  (SM_W2 + HH*W2S)          // 56680
#define SM_B2  (SM_B1 + HH)
#define SM_M   (SM_B2 + HH)
#define SM_OW  (SM_M + HH)
#define SM_OB  (SM_OW + 3*HH)
#define SM_TOT (SM_OB + 4)               // 57452 floats = 229808 bytes

typedef unsigned long long u64;

// persistent scratch (allocation-free rule: __device__ globals)
__device__ float g_xl[(size_t)BB * HH * NN];      // 64 MB, layout (B, H, N)
__device__ float g_part[BB * 64 * HH];            // per-tile pooling partials from local kernel
__device__ float g_part0[BB * 16 * HH];           // partials from projection kernel
__device__ float g_cnt0[BB * 16];
__device__ float g_cnt[BB];
__device__ float g_xg[BB * GG];

__device__ __forceinline__ float lrelu(float v) { return fmaxf(v, 0.01f * v); }

__device__ __forceinline__ u64 pk2(float x, float y) {
    u64 r; asm("mov.b64 %0, {%1,%2};" : "=l"(r) : "f"(x), "f"(y)); return r;
}
__device__ __forceinline__ void upk2(u64 v, float& x, float& y) {
    asm("mov.b64 {%0,%1}, %2;" : "=f"(x), "=f"(y) : "l"(v));
}
__device__ __forceinline__ void fma2(u64& d, u64 a, u64 b) {
    asm("fma.rn.f32x2 %0, %1, %2, %0;" : "+l"(d) : "l"(a), "l"(b));
}

// ---------------------------------------------------------------------------
// K0: xl0 = lrelu(x_local @ proj_lw^T + proj_lb) * mask, stored (B,H,N),
//     plus per-CTA pooling partial sums and mask counts.
// grid (16 b, 16 tiles), 256 threads, 512 points per CTA.
// ---------------------------------------------------------------------------
__global__ __launch_bounds__(256) void k_proj_local(
    const float* __restrict__ x, const float* __restrict__ mask,
    const float* __restrict__ lw, const float* __restrict__ lb)
{
    __shared__ float sw[HH * 3], sb[HH], sp[8][HH], sc[8];
    int b = blockIdx.x, tile = blockIdx.y, tid = threadIdx.x;
    int p0 = tile * 512;
    for (int i = tid; i < HH * 3; i += 256) sw[i] = lw[i];
    for (int i = tid; i < HH; i += 256) sb[i] = lb[i];
    for (int i = tid; i < 8 * HH; i += 256) ((float*)sp)[i] = 0.f;
    __syncthreads();

    int w = tid >> 5, ln = tid & 31;
    float cacc = 0.f;
    for (int gI = 0; gI < 2; ++gI) {
        int p = p0 + w * 64 + gI * 32 + ln;
        const float* xr = x + ((size_t)b * NN + p) * 3;
        float x0 = xr[0], x1 = xr[1], x2 = xr[2];
        float m = mask[(size_t)b * NN + p];
        cacc += m;
        float* orow = g_xl + (size_t)b * HH * NN + p;
        for (int h = 0; h < HH; ++h) {
            float v = fmaf(x0, sw[h * 3], fmaf(x1, sw[h * 3 + 1], fmaf(x2, sw[h * 3 + 2], sb[h])));
            v = lrelu(v) * m;
            orow[(size_t)h * NN] = v;
            float r = v;
            #pragma unroll
            for (int off = 16; off; off >>= 1) r += __shfl_xor_sync(0xffffffffu, r, off);
            if (ln == 0) sp[w][h] += r;
        }
    }
    #pragma unroll
    for (int off = 16; off; off >>= 1) cacc += __shfl_xor_sync(0xffffffffu, cacc, off);
    if (ln == 0) sc[w] = cacc;
    __syncthreads();
    if (tid < HH) {
        float s = 0.f;
        #pragma unroll
        for (int i = 0; i < 8; ++i) s += sp[i][tid];
        g_part0[(b * 16 + tile) * HH + tid] = s;
    }
    if (tid == 0) {
        float c = 0.f;
        for (int i = 0; i < 8; ++i) c += sc[i];
        g_cnt0[b * 16 + tile] = c;
    }
}

// ---------------------------------------------------------------------------
// KG: global path. phase==0: reduce K0 partials, run 3-layer projection
//     global MLP, then EPiC block-0 global. phase==1: reduce local-kernel
//     partials and run EPiC block-`blk` global. grid 16 (b), 128 threads.
// ---------------------------------------------------------------------------
__device__ __forceinline__ float dot_g(const float* __restrict__ w,
                                       const float* __restrict__ xs, int n) {
    float a0 = 0.f, a1 = 0.f, a2 = 0.f, a3 = 0.f;
    int k = 0;
    for (; k + 4 <= n; k += 4) {
        a0 = fmaf(w[k],     xs[k],     a0);
        a1 = fmaf(w[k + 1], xs[k + 1], a1);
        a2 = fmaf(w[k + 2], xs[k + 2], a2);
        a3 = fmaf(w[k + 3], xs[k + 3], a3);
    }
    for (; k < n; ++k) a0 = fmaf(w[k], xs[k], a0);
    return (a0 + a1) + (a2 + a3);
}

__global__ __launch_bounds__(128) void k_global(
    int phase, int blk, const float* __restrict__ ctx,
    const float* __restrict__ pg0w, const float* __restrict__ pg0b,
    const float* __restrict__ pg1w, const float* __restrict__ pg1b,
    const float* __restrict__ pg2w, const float* __restrict__ pg2b,
    const float* __restrict__ g1w, const float* __restrict__ g1b,
    const float* __restrict__ g2w, const float* __restrict__ g2b)
{
    __shared__ float sp[KBLK + 6];
    __shared__ float sh[HH];
    __shared__ float sxg[GG];
    __shared__ float scn;
    int b = blockIdx.x, j = threadIdx.x;

    float s = 0.f;
    if (phase == 0) {
        for (int c = 0; c < 16; ++c) s += g_part0[(b * 16 + c) * HH + j];
        if (j == 0) {
            float cc = 0.f;
            for (int c = 0; c < 16; ++c) cc += g_cnt0[b * 16 + c];
            scn = cc; g_cnt[b] = cc;
        }
    } else {
        for (int c = 0; c < 64; ++c) s += g_part[(b * 64 + c) * HH + j];
        if (j == 0) scn = g_cnt[b];
    }
    __syncthreads();
    float cnt = scn;
    sp[j] = s / cnt;
    sp[HH + j] = s;

    if (phase == 0) {
        if (j < DCC) sp[2 * HH + j] = ctx[b * DCC + j];
        __syncthreads();
        float a = lrelu(dot_g(pg0w + (size_t)j * KPROJ0, sp, KPROJ0) + pg0b[j]);
        __syncthreads();
        sh[j] = a; __syncthreads();
        float a2 = lrelu(dot_g(pg1w + (size_t)j * HH, sh, HH) + pg1b[j]);
        __syncthreads();
        sh[j] = a2; __syncthreads();
        if (j < GG) sxg[j] = lrelu(dot_g(pg2w + (size_t)j * HH, sh, HH) + pg2b[j]);
        __syncthreads();
    } else {
        if (j < GG) sxg[j] = g_xg[b * GG + j];
        __syncthreads();
    }

    // EPiC block `blk` global path: pooled = [mean, sum, xg, ctx]
    if (j < GG)  sp[2 * HH + j] = sxg[j];
    if (j < DCC) sp[2 * HH + GG + j] = ctx[b * DCC + j];
    __syncthreads();
    float hg = lrelu(dot_g(g1w + ((size_t)blk * HH + j) * KBLK, sp, KBLK) + g1b[blk * HH + j]);
    __syncthreads();
    sh[j] = hg; __syncthreads();
    if (j < GG) {
        float a = dot_g(g2w + ((size_t)blk * GG + j) * HH, sh, HH) + g2b[blk * GG + j];
        g_xg[b * GG + j] = lrelu(a + sxg[j]);
    }
}

// ---------------------------------------------------------------------------
// L: per-point two-layer MLP with residual (the heavy kernel).
//    128-point tile per CTA. cat (154x128) and both weight matrices in SMEM.
//    fma.rn.f32x2 packed-fp32 GEMM: each thread owns 8 outputs x 4 point-pairs.
//    Epilogue: residual + lrelu + mask, fused pooling partials, coalesced
//    write-back. Last block computes the output head directly into d_out.
// grid (64 tiles, 16 b), 256 threads, 1 CTA/SM.
// ---------------------------------------------------------------------------
extern __shared__ float smem[];

__global__ void __launch_bounds__(256, 1) k_local(
    int blk, int last,
    const float* __restrict__ l1w, const float* __restrict__ l1b,
    const float* __restrict__ l2w, const float* __restrict__ l2b,
    const float* __restrict__ ctx, const float* __restrict__ mask,
    const float* __restrict__ outw, const float* __restrict__ outb,
    float* __restrict__ dout)
{
    float* s_cat = smem + SM_CAT;
    float* s_buf = smem + SM_BUF;
    float* s_w2  = smem + SM_W2;
    float* s_b1  = smem + SM_B1;
    float* s_b2  = smem + SM_B2;
    float* s_m   = smem + SM_M;
    float* s_ow  = smem + SM_OW;
    float* s_ob  = smem + SM_OB;

    int tile = blockIdx.x, b = blockIdx.y, tid = threadIdx.x;
    int p0 = tile * 128;
    int tj = tid & 15, tp = tid >> 4;

    // ---- loads ----
    {
        const float* xbase = g_xl + (size_t)b * HH * NN + p0;
        for (int idx = tid; idx < HH * 32; idx += 256) {       // xl tile (k-major, point-contiguous)
            int r = idx >> 5, q = idx & 31;
            float4 v = *(const float4*)(xbase + (size_t)r * NN + q * 4);
            *(float4*)(s_cat + r * CATS + q * 4) = v;
        }
        for (int idx = tid; idx < GG * 128; idx += 256) {      // xg rows (broadcast per point)
            int r = idx >> 7, q = idx & 127;
            s_cat[(HH + r) * CATS + q] = g_xg[b * GG + r];
        }
        for (int idx = tid; idx < DCC * 128; idx += 256) {     // ctx rows
            int r = idx >> 7, q = idx & 127;
            s_cat[(HH + GG + r) * CATS + q] = ctx[b * DCC + r];
        }
        const float* w1g = l1w + (size_t)blk * HH * K1;
        for (int idx = tid; idx < HH * K1; idx += 256) {
            int r = idx / K1, c = idx - r * K1;
            s_buf[r * W1S + c] = w1g[idx];
        }
        const float* w2g = l2w + (size_t)blk * HH * HH;
        for (int idx = tid; idx < HH * HH; idx += 256) {
            int r = idx >> 7, c = idx & 127;
            s_w2[r * W2S + c] = w2g[idx];
        }
        if (tid < HH) {
            s_b1[tid] = l1b[blk * HH + tid];
            s_b2[tid] = l2b[blk * HH + tid];
            s_m[tid]  = mask[(size_t)b * NN + p0 + tid];
        }
        if (last) {
            for (int idx = tid; idx < 3 * HH; idx += 256) s_ow[idx] = outw[idx];
            if (tid < 3) s_ob[tid] = outb[tid];
        }
    }
    __syncthreads();

    u64 acc[8][4];

    // ---- stage 1: h_l = lrelu(W1 @ cat + b1) ----
    #pragma unroll
    for (int j = 0; j < 8; ++j)
        #pragma unroll
        for (int i = 0; i < 4; ++i) acc[j][i] = 0ull;

    #pragma unroll 2
    for (int k = 0; k < K1; ++k) {
        u64 a[4];
        #pragma unroll
        for (int i = 0; i < 4; ++i)
            a[i] = *(const u64*)(s_cat + k * CATS + 2 * (tp + 16 * i));
        #pragma unroll
        for (int j = 0; j < 8; ++j) {
            float wv = s_buf[(tj + 16 * j) * W1S + k];
            u64 wd = pk2(wv, wv);
            #pragma unroll
            for (int i = 0; i < 4; ++i) fma2(acc[j][i], a[i], wd);
        }
    }
    #pragma unroll
    for (int j = 0; j < 8; ++j) {
        float bb = s_b1[tj + 16 * j];
        #pragma unroll
        for (int i = 0; i < 4; ++i) {
            float x, y; upk2(acc[j][i], x, y);
            x = lrelu(x + bb); y = lrelu(y + bb);
            acc[j][i] = pk2(x, y);
        }
    }
    __syncthreads();   // everyone done reading w1 before hT overwrites it
    #pragma unroll
    for (int j = 0; j < 8; ++j)
        #pragma unroll
        for (int i = 0; i < 4; ++i)
            *(u64*)(s_buf + ((tj + 16 * j) * HTS + (tp + 16 * i)) * 2) = acc[j][i];
    __syncthreads();

    // ---- stage 2: xl_new = lrelu(W2 @ h_l + b2 + xl) * mask ----
    #pragma unroll
    for (int j = 0; j < 8; ++j)
        #pragma unroll
        for (int i = 0; i < 4; ++i) acc[j][i] = 0ull;

    #pragma unroll 2
    for (int k = 0; k < HH; ++k) {
        u64 a[4];
        #pragma unroll
        for (int i = 0; i < 4; ++i)
            a[i] = *(const u64*)(s_buf + (k * HTS + (tp + 16 * i)) * 2);
        #pragma unroll
        for (int j = 0; j < 8; ++j) {
            float wv = s_w2[(tj + 16 * j) * W2S + k];
            u64 wd = pk2(wv, wv);
            #pragma unroll
            for (int i = 0; i < 4; ++i) fma2(acc[j][i], a[i], wd);
        }
    }
    #pragma unroll
    for (int j = 0; j < 8; ++j) {
        int jr = tj + 16 * j;
        float bb = s_b2[jr];
        #pragma unroll
        for (int i = 0; i < 4; ++i) {
            int pp = tp + 16 * i;
            float x, y; upk2(acc[j][i], x, y);
            float rx = s_cat[jr * CATS + 2 * pp];
            float ry = s_cat[jr * CATS + 2 * pp + 1];
            x = lrelu(x + bb + rx) * s_m[2 * pp];
            y = lrelu(y + bb + ry) * s_m[2 * pp + 1];
            acc[j][i] = pk2(x, y);
        }
    }
    __syncthreads();   // everyone done reading hT before xl_new overwrites it
    #pragma unroll
    for (int j = 0; j < 8; ++j)
        #pragma unroll
        for (int i = 0; i < 4; ++i)
            *(u64*)(s_buf + ((tj + 16 * j) * HTS + (tp + 16 * i)) * 2) = acc[j][i];
    __syncthreads();

    if (!last) {
        // coalesced write-back of xl_new + fused pooling partials
        float* xbase = g_xl + (size_t)b * HH * NN + p0;
        for (int idx = tid; idx < HH * 64; idx += 256) {
            int r = idx >> 6, q = idx & 63;
            *(float2*)(xbase + (size_t)r * NN + 2 * q) =
                *(const float2*)(s_buf + (r * HTS + q) * 2);
        }
        if (tid < HH) {
            const float* row = s_buf + tid * HTS * 2;
            float a0 = 0.f, a1 = 0.f, a2 = 0.f, a3 = 0.f;
            for (int q = 0; q < 128; q += 4) {
                a0 += row[q]; a1 += row[q + 1]; a2 += row[q + 2]; a3 += row[q + 3];
            }
            g_part[(b * 64 + tile) * HH + tid] = (a0 + a1) + (a2 + a3);
        }
    } else {
        // fused output head: out = mask * (xl_new @ outw^T + outb)
        if (tid < 128) {
            int p = tid;
            float m = s_m[p];
            float s0 = s_ob[0], s1 = s_ob[1], s2 = s_ob[2];
            for (int j = 0; j < HH; ++j) {
                float v = s_buf[j * HTS * 2 + p];
                s0 = fmaf(v, s_ow[j], s0);
                s1 = fmaf(v, s_ow[HH + j], s1);
                s2 = fmaf(v, s_ow[2 * HH + j], s2);
            }
            float* o = dout + ((size_t)b * NN + p0 + p) * 3;
            o[0] = m * s0; o[1] = m * s1; o[2] = m * s2;
        }
    }
}

// ---------------------------------------------------------------------------
extern "C" void kernel_launch(void* const* d_in, const int* in_sizes, int n_in,
                              void* d_out, int out_size)
{
    const float* x_local = (const float*)d_in[0];
    const float* context = (const float*)d_in[1];
    const float* mask    = (const float*)d_in[2];
    const float* proj_lw = (const float*)d_in[3];
    const float* proj_lb = (const float*)d_in[4];
    const float* pg0w    = (const float*)d_in[5];
    const float* pg0b    = (const float*)d_in[6];
    const float* pg1w    = (const float*)d_in[7];
    const float* pg1b    = (const float*)d_in[8];
    const float* pg2w    = (const float*)d_in[9];
    const float* pg2b    = (const float*)d_in[10];
    const float* g1w     = (const float*)d_in[11];
    const float* g1b     = (const float*)d_in[12];
    const float* g2w     = (const float*)d_in[13];
    const float* g2b     = (const float*)d_in[14];
    const float* l1w     = (const float*)d_in[15];
    const float* l1b     = (const float*)d_in[16];
    const float* l2w     = (const float*)d_in[17];
    const float* l2b     = (const float*)d_in[18];
    const float* outw    = (const float*)d_in[19];
    const float* outb    = (const float*)d_in[20];
    float* out = (float*)d_out;

    cudaFuncSetAttribute(k_local, cudaFuncAttributeMaxDynamicSharedMemorySize, SM_TOT * 4);

    k_proj_local<<<dim3(16, 16), 256>>>(x_local, mask, proj_lw, proj_lb);
    for (int blk = 0; blk < NBLK; ++blk) {
        k_global<<<16, 128>>>(blk == 0 ? 0 : 1, blk, context,
                              pg0w, pg0b, pg1w, pg1b, pg2w, pg2b,
                              g1w, g1b, g2w, g2b);
        k_local<<<dim3(64, 16), 256, SM_TOT * 4>>>(
            blk, blk == NBLK - 1 ? 1 : 0,
            l1w, l1b, l2w, l2b, context, mask, outw, outb, out);
    }
}

// round 5
// speedup vs baseline: 1.0018x; 1.0018x over previous
#include <cuda_runtime.h>
#include <cstdint>

#define BB 16
#define NN 8192
#define HH 128
#define GG 10
#define DCC 16
#define NBLK 6
#define K1 154        // H + G + DC (local cat width)
#define KPROJ0 272    // 2H + DC
#define KBLK 282      // 2H + G + DC
#define CATS 132      // padded cat row stride (floats)
#define W1S 155       // padded l1w row stride
#define W2S 129       // padded l2w row stride
#define HTS 65        // h_l staging row stride (float2 units)

// SMEM layout for the local kernel (float offsets)
#define SM_CAT 0
#define SM_BUF (K1*CATS)                 // 20328 : w1 (128x155) then reused as hT (128x65 f2)
#define SM_W2  (SM_BUF + HH*W1S)         // 40168 : w2 (128x129)
#define SM_B1  (SM_W2 + HH*W2S)          // 56680
#define SM_B2  (SM_B1 + HH)
#define SM_M   (SM_B2 + HH)
#define SM_OW  (SM_M + HH)
#define SM_OB  (SM_OW + 3*HH)
#define SM_TOT (SM_OB + 4)               // 57452 floats = 229808 bytes

typedef unsigned long long u64;

// persistent scratch (allocation-free rule: __device__ globals)
__device__ float g_xl[(size_t)BB * HH * NN];      // 64 MB, layout (B, H, N)
__device__ float g_part[BB * 64 * HH];            // per-tile pooling partials from local kernel
__device__ float g_part0[BB * 16 * HH];           // partials from projection kernel
__device__ float g_cnt0[BB * 16];
__device__ float g_cnt[BB];
__device__ float g_xg[BB * GG];

__device__ __forceinline__ float lrelu(float v) { return fmaxf(v, 0.01f * v); }

__device__ __forceinline__ u64 pk2(float x, float y) {
    u64 r; asm("mov.b64 %0, {%1,%2};" : "=l"(r) : "f"(x), "f"(y)); return r;
}
__device__ __forceinline__ void upk2(u64 v, float& x, float& y) {
    asm("mov.b64 {%0,%1}, %2;" : "=f"(x), "=f"(y) : "l"(v));
}
__device__ __forceinline__ void fma2(u64& d, u64 a, u64 b) {
    asm("fma.rn.f32x2 %0, %1, %2, %0;" : "+l"(d) : "l"(a), "l"(b));
}

// ---------------------------------------------------------------------------
// K0: xl0 = lrelu(x_local @ proj_lw^T + proj_lb) * mask, stored (B,H,N),
//     plus per-CTA pooling partial sums and mask counts.
// grid (16 b, 16 tiles), 256 threads, 512 points per CTA.
// ---------------------------------------------------------------------------
__global__ __launch_bounds__(256) void k_proj_local(
    const float* __restrict__ x, const float* __restrict__ mask,
    const float* __restrict__ lw, const float* __restrict__ lb)
{
    __shared__ float sw[HH * 3], sb[HH], sp[8][HH], sc[8];
    int b = blockIdx.x, tile = blockIdx.y, tid = threadIdx.x;
    int p0 = tile * 512;
    for (int i = tid; i < HH * 3; i += 256) sw[i] = lw[i];
    for (int i = tid; i < HH; i += 256) sb[i] = lb[i];
    for (int i = tid; i < 8 * HH; i += 256) ((float*)sp)[i] = 0.f;
    __syncthreads();

    int w = tid >> 5, ln = tid & 31;
    float cacc = 0.f;
    for (int gI = 0; gI < 2; ++gI) {
        int p = p0 + w * 64 + gI * 32 + ln;
        const float* xr = x + ((size_t)b * NN + p) * 3;
        float x0 = xr[0], x1 = xr[1], x2 = xr[2];
        float m = mask[(size_t)b * NN + p];
        cacc += m;
        float* orow = g_xl + (size_t)b * HH * NN + p;
        for (int h = 0; h < HH; ++h) {
            float v = fmaf(x0, sw[h * 3], fmaf(x1, sw[h * 3 + 1], fmaf(x2, sw[h * 3 + 2], sb[h])));
            v = lrelu(v) * m;
            orow[(size_t)h * NN] = v;
            float r = v;
            #pragma unroll
            for (int off = 16; off; off >>= 1) r += __shfl_xor_sync(0xffffffffu, r, off);
            if (ln == 0) sp[w][h] += r;
        }
    }
    #pragma unroll
    for (int off = 16; off; off >>= 1) cacc += __shfl_xor_sync(0xffffffffu, cacc, off);
    if (ln == 0) sc[w] = cacc;
    __syncthreads();
    if (tid < HH) {
        float s = 0.f;
        #pragma unroll
        for (int i = 0; i < 8; ++i) s += sp[i][tid];
        g_part0[(b * 16 + tile) * HH + tid] = s;
    }
    if (tid == 0) {
        float c = 0.f;
        for (int i = 0; i < 8; ++i) c += sc[i];
        g_cnt0[b * 16 + tile] = c;
    }
}

// ---------------------------------------------------------------------------
// KG: global path. phase==0: reduce K0 partials, run 3-layer projection
//     global MLP, then EPiC block-0 global. phase==1: reduce local-kernel
//     partials and run EPiC block-`blk` global. grid 16 (b), 128 threads.
// ---------------------------------------------------------------------------
__device__ __forceinline__ float dot_g(const float* __restrict__ w,
                                       const float* __restrict__ xs, int n) {
    float a0 = 0.f, a1 = 0.f, a2 = 0.f, a3 = 0.f;
    int k = 0;
    for (; k + 4 <= n; k += 4) {
        a0 = fmaf(w[k],     xs[k],     a0);
        a1 = fmaf(w[k + 1], xs[k + 1], a1);
        a2 = fmaf(w[k + 2], xs[k + 2], a2);
        a3 = fmaf(w[k + 3], xs[k + 3], a3);
    }
    for (; k < n; ++k) a0 = fmaf(w[k], xs[k], a0);
    return (a0 + a1) + (a2 + a3);
}

__global__ __launch_bounds__(128) void k_global(
    int phase, int blk, const float* __restrict__ ctx,
    const float* __restrict__ pg0w, const float* __restrict__ pg0b,
    const float* __restrict__ pg1w, const float* __restrict__ pg1b,
    const float* __restrict__ pg2w, const float* __restrict__ pg2b,
    const float* __restrict__ g1w, const float* __restrict__ g1b,
    const float* __restrict__ g2w, const float* __restrict__ g2b)
{
    __shared__ float sp[KBLK + 6];
    __shared__ float sh[HH];
    __shared__ float sxg[GG];
    __shared__ float scn;
    int b = blockIdx.x, j = threadIdx.x;

    float s = 0.f;
    if (phase == 0) {
        for (int c = 0; c < 16; ++c) s += g_part0[(b * 16 + c) * HH + j];
        if (j == 0) {
            float cc = 0.f;
            for (int c = 0; c < 16; ++c) cc += g_cnt0[b * 16 + c];
            scn = cc; g_cnt[b] = cc;
        }
    } else {
        for (int c = 0; c < 64; ++c) s += g_part[(b * 64 + c) * HH + j];
        if (j == 0) scn = g_cnt[b];
    }
    __syncthreads();
    float cnt = scn;
    sp[j] = s / cnt;
    sp[HH + j] = s;

    if (phase == 0) {
        if (j < DCC) sp[2 * HH + j] = ctx[b * DCC + j];
        __syncthreads();
        float a = lrelu(dot_g(pg0w + (size_t)j * KPROJ0, sp, KPROJ0) + pg0b[j]);
        __syncthreads();
        sh[j] = a; __syncthreads();
        float a2 = lrelu(dot_g(pg1w + (size_t)j * HH, sh, HH) + pg1b[j]);
        __syncthreads();
        sh[j] = a2; __syncthreads();
        if (j < GG) sxg[j] = lrelu(dot_g(pg2w + (size_t)j * HH, sh, HH) + pg2b[j]);
        __syncthreads();
    } else {
        if (j < GG) sxg[j] = g_xg[b * GG + j];
        __syncthreads();
    }

    // EPiC block `blk` global path: pooled = [mean, sum, xg, ctx]
    if (j < GG)  sp[2 * HH + j] = sxg[j];
    if (j < DCC) sp[2 * HH + GG + j] = ctx[b * DCC + j];
    __syncthreads();
    float hg = lrelu(dot_g(g1w + ((size_t)blk * HH + j) * KBLK, sp, KBLK) + g1b[blk * HH + j]);
    __syncthreads();
    sh[j] = hg; __syncthreads();
    if (j < GG) {
        float a = dot_g(g2w + ((size_t)blk * GG + j) * HH, sh, HH) + g2b[blk * GG + j];
        g_xg[b * GG + j] = lrelu(a + sxg[j]);
    }
}

// ---------------------------------------------------------------------------
// L: per-point two-layer MLP with residual (the heavy kernel).
//    128-point tile per CTA. cat (154x128) and both weight matrices in SMEM.
//    fma.rn.f32x2 packed-fp32 GEMM: each thread owns 8 outputs x 4 point-pairs.
//    Epilogue: residual + lrelu + mask, fused pooling partials, coalesced
//    write-back. Last block computes the output head directly into d_out.
// grid (64 tiles, 16 b), 256 threads, 1 CTA/SM.
// ---------------------------------------------------------------------------
extern __shared__ float smem[];

__global__ void __launch_bounds__(256, 1) k_local(
    int blk, int last,
    const float* __restrict__ l1w, const float* __restrict__ l1b,
    const float* __restrict__ l2w, const float* __restrict__ l2b,
    const float* __restrict__ ctx, const float* __restrict__ mask,
    const float* __restrict__ outw, const float* __restrict__ outb,
    float* __restrict__ dout)
{
    float* s_cat = smem + SM_CAT;
    float* s_buf = smem + SM_BUF;
    float* s_w2  = smem + SM_W2;
    float* s_b1  = smem + SM_B1;
    float* s_b2  = smem + SM_B2;
    float* s_m   = smem + SM_M;
    float* s_ow  = smem + SM_OW;
    float* s_ob  = smem + SM_OB;

    int tile = blockIdx.x, b = blockIdx.y, tid = threadIdx.x;
    int p0 = tile * 128;
    int tj = tid & 15, tp = tid >> 4;

    // ---- loads ----
    {
        const float* xbase = g_xl + (size_t)b * HH * NN + p0;
        for (int idx = tid; idx < HH * 32; idx += 256) {       // xl tile (k-major, point-contiguous)
            int r = idx >> 5, q = idx & 31;
            float4 v = *(const float4*)(xbase + (size_t)r * NN + q * 4);
            *(float4*)(s_cat + r * CATS + q * 4) = v;
        }
        for (int idx = tid; idx < GG * 128; idx += 256) {      // xg rows (broadcast per point)
            int r = idx >> 7, q = idx & 127;
            s_cat[(HH + r) * CATS + q] = g_xg[b * GG + r];
        }
        for (int idx = tid; idx < DCC * 128; idx += 256) {     // ctx rows
            int r = idx >> 7, q = idx & 127;
            s_cat[(HH + GG + r) * CATS + q] = ctx[b * DCC + r];
        }
        const float* w1g = l1w + (size_t)blk * HH * K1;
        for (int idx = tid; idx < HH * K1; idx += 256) {
            int r = idx / K1, c = idx - r * K1;
            s_buf[r * W1S + c] = w1g[idx];
        }
        const float* w2g = l2w + (size_t)blk * HH * HH;
        for (int idx = tid; idx < HH * HH; idx += 256) {
            int r = idx >> 7, c = idx & 127;
            s_w2[r * W2S + c] = w2g[idx];
        }
        if (tid < HH) {
            s_b1[tid] = l1b[blk * HH + tid];
            s_b2[tid] = l2b[blk * HH + tid];
            s_m[tid]  = mask[(size_t)b * NN + p0 + tid];
        }
        if (last) {
            for (int idx = tid; idx < 3 * HH; idx += 256) s_ow[idx] = outw[idx];
            if (tid < 3) s_ob[tid] = outb[tid];
        }
    }
    __syncthreads();

    u64 acc[8][4];

    // ---- stage 1: h_l = lrelu(W1 @ cat + b1) ----
    #pragma unroll
    for (int j = 0; j < 8; ++j)
        #pragma unroll
        for (int i = 0; i < 4; ++i) acc[j][i] = 0ull;

    #pragma unroll 2
    for (int k = 0; k < K1; ++k) {
        u64 a[4];
        #pragma unroll
        for (int i = 0; i < 4; ++i)
            a[i] = *(const u64*)(s_cat + k * CATS + 2 * (tp + 16 * i));
        #pragma unroll
        for (int j = 0; j < 8; ++j) {
            float wv = s_buf[(tj + 16 * j) * W1S + k];
            u64 wd = pk2(wv, wv);
            #pragma unroll
            for (int i = 0; i < 4; ++i) fma2(acc[j][i], a[i], wd);
        }
    }
    #pragma unroll
    for (int j = 0; j < 8; ++j) {
        float bb = s_b1[tj + 16 * j];
        #pragma unroll
        for (int i = 0; i < 4; ++i) {
            float x, y; upk2(acc[j][i], x, y);
            x = lrelu(x + bb); y = lrelu(y + bb);
            acc[j][i] = pk2(x, y);
        }
    }
    __syncthreads();   // everyone done reading w1 before hT overwrites it
    #pragma unroll
    for (int j = 0; j < 8; ++j)
        #pragma unroll
        for (int i = 0; i < 4; ++i)
            *(u64*)(s_buf + ((tj + 16 * j) * HTS + (tp + 16 * i)) * 2) = acc[j][i];
    __syncthreads();

    // ---- stage 2: xl_new = lrelu(W2 @ h_l + b2 + xl) * mask ----
    #pragma unroll
    for (int j = 0; j < 8; ++j)
        #pragma unroll
        for (int i = 0; i < 4; ++i) acc[j][i] = 0ull;

    #pragma unroll 2
    for (int k = 0; k < HH; ++k) {
        u64 a[4];
        #pragma unroll
        for (int i = 0; i < 4; ++i)
            a[i] = *(const u64*)(s_buf + (k * HTS + (tp + 16 * i)) * 2);
        #pragma unroll
        for (int j = 0; j < 8; ++j) {
            float wv = s_w2[(tj + 16 * j) * W2S + k];
            u64 wd = pk2(wv, wv);
            #pragma unroll
            for (int i = 0; i < 4; ++i) fma2(acc[j][i], a[i], wd);
        }
    }
    #pragma unroll
    for (int j = 0; j < 8; ++j) {
        int jr = tj + 16 * j;
        float bb = s_b2[jr];
        #pragma unroll
        for (int i = 0; i < 4; ++i) {
            int pp = tp + 16 * i;
            float x, y; upk2(acc[j][i], x, y);
            float rx = s_cat[jr * CATS + 2 * pp];
            float ry = s_cat[jr * CATS + 2 * pp + 1];
            x = lrelu(x + bb + rx) * s_m[2 * pp];
            y = lrelu(y + bb + ry) * s_m[2 * pp + 1];
            acc[j][i] = pk2(x, y);
        }
    }
    __syncthreads();   // everyone done reading hT before xl_new overwrites it
    #pragma unroll
    for (int j = 0; j < 8; ++j)
        #pragma unroll
        for (int i = 0; i < 4; ++i)
            *(u64*)(s_buf + ((tj + 16 * j) * HTS + (tp + 16 * i)) * 2) = acc[j][i];
    __syncthreads();

    if (!last) {
        // coalesced write-back of xl_new + fused pooling partials
        float* xbase = g_xl + (size_t)b * HH * NN + p0;
        for (int idx = tid; idx < HH * 64; idx += 256) {
            int r = idx >> 6, q = idx & 63;
            *(float2*)(xbase + (size_t)r * NN + 2 * q) =
                *(const float2*)(s_buf + (r * HTS + q) * 2);
        }
        if (tid < HH) {
            const float* row = s_buf + tid * HTS * 2;
            float a0 = 0.f, a1 = 0.f, a2 = 0.f, a3 = 0.f;
            for (int q = 0; q < 128; q += 4) {
                a0 += row[q]; a1 += row[q + 1]; a2 += row[q + 2]; a3 += row[q + 3];
            }
            g_part[(b * 64 + tile) * HH + tid] = (a0 + a1) + (a2 + a3);
        }
    } else {
        // fused output head: out = mask * (xl_new @ outw^T + outb)
        if (tid < 128) {
            int p = tid;
            float m = s_m[p];
            float s0 = s_ob[0], s1 = s_ob[1], s2 = s_ob[2];
            for (int j = 0; j < HH; ++j) {
                float v = s_buf[j * HTS * 2 + p];
                s0 = fmaf(v, s_ow[j], s0);
                s1 = fmaf(v, s_ow[HH + j], s1);
                s2 = fmaf(v, s_ow[2 * HH + j], s2);
            }
            float* o = dout + ((size_t)b * NN + p0 + p) * 3;
            o[0] = m * s0; o[1] = m * s1; o[2] = m * s2;
        }
    }
}

// ---------------------------------------------------------------------------
extern "C" void kernel_launch(void* const* d_in, const int* in_sizes, int n_in,
                              void* d_out, int out_size)
{
    const float* x_local = (const float*)d_in[0];
    const float* context = (const float*)d_in[1];
    const float* mask    = (const float*)d_in[2];
    const float* proj_lw = (const float*)d_in[3];
    const float* proj_lb = (const float*)d_in[4];
    const float* pg0w    = (const float*)d_in[5];
    const float* pg0b    = (const float*)d_in[6];
    const float* pg1w    = (const float*)d_in[7];
    const float* pg1b    = (const float*)d_in[8];
    const float* pg2w    = (const float*)d_in[9];
    const float* pg2b    = (const float*)d_in[10];
    const float* g1w     = (const float*)d_in[11];
    const float* g1b     = (const float*)d_in[12];
    const float* g2w     = (const float*)d_in[13];
    const float* g2b     = (const float*)d_in[14];
    const float* l1w     = (const float*)d_in[15];
    const float* l1b     = (const float*)d_in[16];
    const float* l2w     = (const float*)d_in[17];
    const float* l2b     = (const float*)d_in[18];
    const float* outw    = (const float*)d_in[19];
    const float* outb    = (const float*)d_in[20];
    float* out = (float*)d_out;

    cudaFuncSetAttribute(k_local, cudaFuncAttributeMaxDynamicSharedMemorySize, SM_TOT * 4);

    k_proj_local<<<dim3(16, 16), 256>>>(x_local, mask, proj_lw, proj_lb);
    for (int blk = 0; blk < NBLK; ++blk) {
        k_global<<<16, 128>>>(blk == 0 ? 0 : 1, blk, context,
                              pg0w, pg0b, pg1w, pg1b, pg2w, pg2b,
                              g1w, g1b, g2w, g2b);
        k_local<<<dim3(64, 16), 256, SM_TOT * 4>>>(
            blk, blk == NBLK - 1 ? 1 : 0,
            l1w, l1b, l2w, l2b, context, mask, outw, outb, out);
    }
}